// round 1
// baseline (speedup 1.0000x reference)
#include <cuda_runtime.h>

// PyramidROIAlign: B=2, N=1000 boxes, C=256 channels, 7x7 pool.
// Inputs (metadata order): boxes [B,N,4] f32, image_shape [2] f32,
//   P2 [B,256,256,256] f32, P3 [B,128,128,256], P4 [B,64,64,256], P5 [B,32,32,256]
// Output: [B,N,7,7,256] f32.

#define POOL 7
#define NPTS (POOL * POOL)
#define CCH 256
#define C4 (CCH / 4)

__global__ void __launch_bounds__(256)
roi_align_kernel(const float* __restrict__ boxes,
                 const float* __restrict__ image_shape,
                 const float* __restrict__ P2,
                 const float* __restrict__ P3,
                 const float* __restrict__ P4,
                 const float* __restrict__ P5,
                 float* __restrict__ out,
                 int total_boxes, int boxes_per_batch)
{
    const long long g = (long long)blockIdx.x * blockDim.x + threadIdx.x;
    const int item = (int)(g >> 6);          // (box, grid-point) index
    const int lane = (int)(g & 63);          // float4 lane within C=256
    const int total_items = total_boxes * NPTS;
    if (item >= total_items) return;

    const int bn = item / NPTS;
    const int pt = item - bn * NPTS;
    const int py = pt / POOL;
    const int px = pt - py * POOL;
    const int b  = bn / boxes_per_batch;

    // Box (normalized y1,x1,y2,x2)
    const float4 bx = ((const float4*)boxes)[bn];
    const float y1 = bx.x, x1 = bx.y, y2 = bx.z, x2 = bx.w;
    const float h = y2 - y1;
    const float w = x2 - x1;

    // Level: lvl = clamp(4 + round(log2(sqrt(h*w) / (224/sqrt(area)))), 2, 5)
    // Mirror reference fp32 op order; rintf == round-half-to-even == jnp.round.
    const float area = image_shape[0] * image_shape[1];
    float lvlf = log2f(sqrtf(h * w) / (224.0f / sqrtf(area)));
    lvlf = fminf(5.0f, fmaxf(2.0f, 4.0f + rintf(lvlf)));
    const int lvl = (int)lvlf;

    const float* fmap;
    int H;
    if (lvl == 2)      { fmap = P2; H = 256; }
    else if (lvl == 3) { fmap = P3; H = 128; }
    else if (lvl == 4) { fmap = P4; H = 64;  }
    else               { fmap = P5; H = 32;  }
    const int W = H;

    // Sample coordinate (reference order: (y1 + h*gy) * (H-1))
    const float gy = (float)py / 6.0f;
    const float gx = (float)px / 6.0f;
    const float in_y = (y1 + h * gy) * (float)(H - 1);
    const float in_x = (x1 + w * gx) * (float)(W - 1);

    const float y0f = floorf(in_y);
    const float x0f = floorf(in_x);
    const float wy = in_y - y0f;   // unclipped fractional weights (reference)
    const float wx = in_x - x0f;

    int y0  = (int)y0f; y0  = min(max(y0, 0), H - 1);
    int y1i = min(y0 + 1, H - 1);
    int x0  = (int)x0f; x0  = min(max(x0, 0), W - 1);
    int x1i = min(x0 + 1, W - 1);

    const size_t batch_base = (size_t)b * H * W * CCH;
    const float4* tl = (const float4*)(fmap + batch_base + ((size_t)y0  * W + x0 ) * CCH);
    const float4* tr = (const float4*)(fmap + batch_base + ((size_t)y0  * W + x1i) * CCH);
    const float4* bl = (const float4*)(fmap + batch_base + ((size_t)y1i * W + x0 ) * CCH);
    const float4* br = (const float4*)(fmap + batch_base + ((size_t)y1i * W + x1i) * CCH);

    const float4 vtl = tl[lane];
    const float4 vtr = tr[lane];
    const float4 vbl = bl[lane];
    const float4 vbr = br[lane];

    // top = tl + (tr-tl)*wx; bot = bl + (br-bl)*wx; out = top + (bot-top)*wy
    float4 r;
    {
        float t, bt;
        t  = vtl.x + (vtr.x - vtl.x) * wx;
        bt = vbl.x + (vbr.x - vbl.x) * wx;
        r.x = t + (bt - t) * wy;
        t  = vtl.y + (vtr.y - vtl.y) * wx;
        bt = vbl.y + (vbr.y - vbl.y) * wx;
        r.y = t + (bt - t) * wy;
        t  = vtl.z + (vtr.z - vtl.z) * wx;
        bt = vbl.z + (vbr.z - vbl.z) * wx;
        r.z = t + (bt - t) * wy;
        t  = vtl.w + (vtr.w - vtl.w) * wx;
        bt = vbl.w + (vbr.w - vbl.w) * wx;
        r.w = t + (bt - t) * wy;
    }

    ((float4*)out)[(size_t)item * C4 + lane] = r;
}

extern "C" void kernel_launch(void* const* d_in, const int* in_sizes, int n_in,
                              void* d_out, int out_size)
{
    const float* boxes = (const float*)d_in[0];
    const float* ishp  = (const float*)d_in[1];
    const float* P2    = (const float*)d_in[2];
    const float* P3    = (const float*)d_in[3];
    const float* P4    = (const float*)d_in[4];
    const float* P5    = (const float*)d_in[5];
    float* out = (float*)d_out;

    // B from P2 element count: B * 256*256*256
    const int B = in_sizes[2] / (256 * 256 * 256);
    const int total_boxes = in_sizes[0] / 4;           // B*N
    const int boxes_per_batch = total_boxes / B;       // N

    const long long total_threads = (long long)total_boxes * NPTS * 64;
    const int threads = 256;
    const int blocks = (int)((total_threads + threads - 1) / threads);

    roi_align_kernel<<<blocks, threads>>>(boxes, ishp, P2, P3, P4, P5, out,
                                          total_boxes, boxes_per_batch);
}

// round 2
// speedup vs baseline: 1.5400x; 1.5400x over previous
#include <cuda_runtime.h>

// PyramidROIAlign: B=2, N=1000 boxes, C=256 channels, 7x7 pool.
// Two-phase: (A) per-item param kernel -> scratch; (B) lean gather/lerp kernel.

#define POOL 7
#define NPTS (POOL * POOL)
#define CCH 256
#define C4 (CCH / 4)
#define LANES 16               // threads per item in kernel B (each does 4 float4)
#define MAX_ITEMS (131072)     // >= B*N*49 (98000 for B=2,N=1000)

// Scratch: 4 corner addresses + 2 weights per item.
__device__ ulonglong4 g_addr[MAX_ITEMS];   // tl, tr, bl, br absolute addresses
__device__ float2     g_w[MAX_ITEMS];      // wx, wy

__global__ void __launch_bounds__(256)
roi_params_kernel(const float* __restrict__ boxes,
                  const float* __restrict__ image_shape,
                  const float* __restrict__ P2,
                  const float* __restrict__ P3,
                  const float* __restrict__ P4,
                  const float* __restrict__ P5,
                  int total_items, int boxes_per_batch)
{
    const int item = blockIdx.x * blockDim.x + threadIdx.x;
    if (item >= total_items) return;

    const int bn = item / NPTS;
    const int pt = item - bn * NPTS;
    const int py = pt / POOL;
    const int px = pt - py * POOL;
    const int b  = bn / boxes_per_batch;

    const float4 bx = ((const float4*)boxes)[bn];
    const float y1 = bx.x, x1 = bx.y, y2 = bx.z, x2 = bx.w;
    const float h = y2 - y1;
    const float w = x2 - x1;

    // Level selection — mirror reference fp32 op order; rintf == jnp.round.
    const float area = image_shape[0] * image_shape[1];
    float lvlf = log2f(sqrtf(h * w) / (224.0f / sqrtf(area)));
    lvlf = fminf(5.0f, fmaxf(2.0f, 4.0f + rintf(lvlf)));
    const int lvl = (int)lvlf;

    const float* fmap;
    int H;
    if (lvl == 2)      { fmap = P2; H = 256; }
    else if (lvl == 3) { fmap = P3; H = 128; }
    else if (lvl == 4) { fmap = P4; H = 64;  }
    else               { fmap = P5; H = 32;  }
    const int W = H;

    const float gy = (float)py / 6.0f;
    const float gx = (float)px / 6.0f;
    const float in_y = (y1 + h * gy) * (float)(H - 1);
    const float in_x = (x1 + w * gx) * (float)(W - 1);

    const float y0f = floorf(in_y);
    const float x0f = floorf(in_x);
    const float wy = in_y - y0f;
    const float wx = in_x - x0f;

    int y0  = (int)y0f; y0  = min(max(y0, 0), H - 1);
    int y1i = min(y0 + 1, H - 1);
    int x0  = (int)x0f; x0  = min(max(x0, 0), W - 1);
    int x1i = min(x0 + 1, W - 1);

    const unsigned long long base =
        (unsigned long long)fmap + (unsigned long long)b * H * W * CCH * 4ull;
    const unsigned long long rowT = base + (unsigned long long)(y0  * W) * (CCH * 4ull);
    const unsigned long long rowB = base + (unsigned long long)(y1i * W) * (CCH * 4ull);

    ulonglong4 a;
    a.x = rowT + (unsigned long long)x0  * (CCH * 4ull);  // tl
    a.y = rowT + (unsigned long long)x1i * (CCH * 4ull);  // tr
    a.z = rowB + (unsigned long long)x0  * (CCH * 4ull);  // bl
    a.w = rowB + (unsigned long long)x1i * (CCH * 4ull);  // br
    g_addr[item] = a;
    g_w[item] = make_float2(wx, wy);
}

__global__ void __launch_bounds__(256)
roi_gather_kernel(float* __restrict__ out, int total_items)
{
    const long long g = (long long)blockIdx.x * blockDim.x + threadIdx.x;
    const int item = (int)(g >> 4);
    const int lane = (int)(g & (LANES - 1));
    if (item >= total_items) return;

    const ulonglong4 a = g_addr[item];   // broadcast across 16 lanes via L1
    const float2 wv = g_w[item];
    const float wx = wv.x, wy = wv.y;

    const float4* __restrict__ tl = (const float4*)a.x;
    const float4* __restrict__ tr = (const float4*)a.y;
    const float4* __restrict__ bl = (const float4*)a.z;
    const float4* __restrict__ br = (const float4*)a.w;
    float4* __restrict__ o = (float4*)(out + (size_t)item * CCH);

#pragma unroll
    for (int j = 0; j < 4; j++) {
        const int c = lane + j * LANES;       // strided: each LDG fully coalesced
        const float4 vtl = tl[c];
        const float4 vtr = tr[c];
        const float4 vbl = bl[c];
        const float4 vbr = br[c];
        float4 r;
        float t, bt;
        t  = vtl.x + (vtr.x - vtl.x) * wx;
        bt = vbl.x + (vbr.x - vbl.x) * wx;
        r.x = t + (bt - t) * wy;
        t  = vtl.y + (vtr.y - vtl.y) * wx;
        bt = vbl.y + (vbr.y - vbl.y) * wx;
        r.y = t + (bt - t) * wy;
        t  = vtl.z + (vtr.z - vtl.z) * wx;
        bt = vbl.z + (vbr.z - vbl.z) * wx;
        r.z = t + (bt - t) * wy;
        t  = vtl.w + (vtr.w - vtl.w) * wx;
        bt = vbl.w + (vbr.w - vbl.w) * wx;
        r.w = t + (bt - t) * wy;
        o[c] = r;
    }
}

extern "C" void kernel_launch(void* const* d_in, const int* in_sizes, int n_in,
                              void* d_out, int out_size)
{
    const float* boxes = (const float*)d_in[0];
    const float* ishp  = (const float*)d_in[1];
    const float* P2    = (const float*)d_in[2];
    const float* P3    = (const float*)d_in[3];
    const float* P4    = (const float*)d_in[4];
    const float* P5    = (const float*)d_in[5];
    float* out = (float*)d_out;

    const int B = in_sizes[2] / (256 * 256 * 256);
    const int total_boxes = in_sizes[0] / 4;
    const int boxes_per_batch = total_boxes / B;
    const int total_items = total_boxes * NPTS;

    {
        const int threads = 256;
        const int blocks = (total_items + threads - 1) / threads;
        roi_params_kernel<<<blocks, threads>>>(boxes, ishp, P2, P3, P4, P5,
                                               total_items, boxes_per_batch);
    }
    {
        const long long total_threads = (long long)total_items * LANES;
        const int threads = 256;
        const int blocks = (int)((total_threads + threads - 1) / threads);
        roi_gather_kernel<<<blocks, threads>>>(out, total_items);
    }
}